// round 2
// baseline (speedup 1.0000x reference)
#include <cuda_runtime.h>

#define KPTS   16384
#define NATOMS 1024
#define NB     16
#define NSRC   17   // source 0 = C, sources 1..16 = C1[b]

// L = inv2s * log2(e) = 2*pi * 1.4426950408889634
#define LCONST 9.064720283654388f

// scratch: static device arrays (no allocation allowed)
__device__ float4 g_atoms[NSRC * NATOMS];
__device__ float  g_theta[NSRC * KPTS];

// ---------------------------------------------------------------------------
// Precompute per-atom coefficients: (2L*x, 2L*y, 2L*z, -L*|x|^2)
// so exp(-inv2s*||d-x||^2) = exp2( ax*dx + ay*dy + az*dz + aw + c )
// with c = -L*|d|^2 per grid point.
// ---------------------------------------------------------------------------
__global__ void prep_kernel(const float* __restrict__ C1,
                            const float* __restrict__ C) {
    int i = blockIdx.x * blockDim.x + threadIdx.x;
    if (i >= NSRC * NATOMS) return;
    float x, y, z;
    if (i < NATOMS) {
        x = C[i * 3 + 0]; y = C[i * 3 + 1]; z = C[i * 3 + 2];
    } else {
        int j = i - NATOMS;            // flat over (b, n) matches C1 row-major
        x = C1[j * 3 + 0]; y = C1[j * 3 + 1]; z = C1[j * 3 + 2];
    }
    float phi = x * x + y * y + z * z;
    g_atoms[i] = make_float4(2.f * LCONST * x, 2.f * LCONST * y,
                             2.f * LCONST * z, -LCONST * phi);
}

// ---------------------------------------------------------------------------
// theta[s][k] = sum_n exp(-inv2s * ||dom_k - atom_{s,n}||^2)
// grid: (KPTS/256, NSRC). Each block caches one 16KB atom source in SMEM
// (uniform broadcast reads in the inner loop), each thread owns one k.
// ---------------------------------------------------------------------------
__global__ void __launch_bounds__(256) theta_kernel(const float* __restrict__ dom) {
    __shared__ float4 tile[NATOMS];
    const int s = blockIdx.y;
    const int k = blockIdx.x * 256 + threadIdx.x;

    const float4* src = g_atoms + s * NATOMS;
    #pragma unroll
    for (int j = 0; j < NATOMS / 256; ++j)
        tile[threadIdx.x + j * 256] = src[threadIdx.x + j * 256];

    const float kx = dom[k * 3 + 0];
    const float ky = dom[k * 3 + 1];
    const float kz = dom[k * 3 + 2];
    const float c  = -LCONST * (kx * kx + ky * ky + kz * kz);
    __syncthreads();

    float acc = 0.f;
    #pragma unroll 8
    for (int j = 0; j < NATOMS; ++j) {
        float4 a = tile[j];
        float arg = fmaf(kx, a.x, fmaf(ky, a.y, fmaf(kz, a.z, a.w))) + c;
        float e;
        asm("ex2.approx.ftz.f32 %0, %1;" : "=f"(e) : "f"(arg));
        acc += e;
    }
    g_theta[s * KPTS + k] = acc;
}

// ---------------------------------------------------------------------------
// out[b] = 1 - clip( A*V/sqrt(n1*n2) * sum_k theta[b+1][k]*theta[0][k], 0, 1 )
// A = (2*pi*sigma)^-3 = 8, V = 1000/16384, sqrt(n1*n2) = 1024
// scale = 8 * (1000/16384) / 1024 = 4.76837158203125e-4
// Deterministic tree reduction (no float atomics -> graph-replay stable).
// ---------------------------------------------------------------------------
__global__ void reduce_kernel(float* __restrict__ out) {
    __shared__ float red[256];
    const int b = blockIdx.x;
    const float* tb = g_theta + (1 + b) * KPTS;
    const float* t0 = g_theta;
    float p = 0.f;
    for (int k = threadIdx.x; k < KPTS; k += 256)
        p += tb[k] * t0[k];
    red[threadIdx.x] = p;
    __syncthreads();
    for (int st = 128; st > 0; st >>= 1) {
        if (threadIdx.x < st) red[threadIdx.x] += red[threadIdx.x + st];
        __syncthreads();
    }
    if (threadIdx.x == 0) {
        float dot = 4.76837158203125e-4f * red[0];
        dot = fminf(fmaxf(dot, 0.f), 1.f);
        out[b] = 1.f - dot;
    }
}

extern "C" void kernel_launch(void* const* d_in, const int* in_sizes, int n_in,
                              void* d_out, int out_size) {
    const float* C1  = (const float*)d_in[0];   // (16, 1024, 3)
    const float* C   = (const float*)d_in[1];   // (1024, 3)
    const float* dom = (const float*)d_in[2];   // (16384, 3)

    prep_kernel<<<(NSRC * NATOMS + 255) / 256, 256>>>(C1, C);
    theta_kernel<<<dim3(KPTS / 256, NSRC), 256>>>(dom);
    reduce_kernel<<<NB, 256>>>((float*)d_out);
}

// round 3
// speedup vs baseline: 1.6031x; 1.6031x over previous
#include <cuda_runtime.h>

#define KPTS   16384
#define NATOMS 1024
#define NB     16
#define NSRC   17      // source 0 = C, sources 1..16 = C1[b]
#define NC     5       // cells per axis (h = 2.0)
#define NCELLS 125
#define ACAP   40      // atoms per cell capacity (mean 8.2, ~11 sigma)
#define DCAP   512     // dom points per cell capacity (mean 131)
#define CCAP   80      // dom points per (cell, 2048-chunk) capacity (mean 16.4)
#define SCAP   448     // gathered neighbor-atom capacity (mean 221, ~15 sigma)

// L = inv2s * log2(e) = 2*pi * 1.4426950408889634
#define LCONST 9.064720283654388f

// static scratch (no allocations allowed)
__device__ float4 g_binned[NSRC * NCELLS * ACAP];
__device__ int    g_acount[NSRC * NCELLS];
__device__ int    g_dlist[NCELLS * DCAP];
__device__ int    g_dcount[NCELLS];
__device__ float4 g_kcoef[KPTS];
__device__ float  g_theta[NSRC * KPTS];

__device__ __forceinline__ int cell_of(float x, float y, float z) {
    int cx = min(NC - 1, max(0, (int)(x * 0.5f)));
    int cy = min(NC - 1, max(0, (int)(y * 0.5f)));
    int cz = min(NC - 1, max(0, (int)(z * 0.5f)));
    return (cz * NC + cy) * NC + cx;
}

// ---------------------------------------------------------------------------
// One warp per (cell, source): ballot-compact atoms of this source whose cell
// matches, storing precomputed coefficients (2L*x, 2L*y, 2L*z, -L*|x|^2).
// Deterministic: compaction preserves atom index order.
// ---------------------------------------------------------------------------
__global__ void bin_atoms_kernel(const float* __restrict__ C1,
                                 const float* __restrict__ C) {
    const int cell = blockIdx.x;
    const int s    = blockIdx.y;
    const float* src = (s == 0) ? C : (C1 + (size_t)(s - 1) * NATOMS * 3);
    const int lane = threadIdx.x;
    float4* dst = g_binned + (s * NCELLS + cell) * ACAP;

    int base = 0;
    for (int j0 = 0; j0 < NATOMS; j0 += 32) {
        int j = j0 + lane;
        float x = src[j * 3 + 0];
        float y = src[j * 3 + 1];
        float z = src[j * 3 + 2];
        bool m = (cell_of(x, y, z) == cell);
        unsigned mask = __ballot_sync(0xffffffffu, m);
        if (m) {
            int pos = base + __popc(mask & ((1u << lane) - 1u));
            if (pos < ACAP) {
                float phi = x * x + y * y + z * z;
                dst[pos] = make_float4(2.f * LCONST * x, 2.f * LCONST * y,
                                       2.f * LCONST * z, -LCONST * phi);
            }
        }
        base += __popc(mask);
    }
    if (lane == 0) g_acount[s * NCELLS + cell] = min(base, ACAP);
}

// ---------------------------------------------------------------------------
// One block (8 warps) per cell: each warp compacts a disjoint 2048-point
// chunk into smem, then chunks are concatenated in order. Deterministic.
// ---------------------------------------------------------------------------
__global__ void __launch_bounds__(256) bin_dom_kernel(const float* __restrict__ dom) {
    __shared__ int lists[8 * CCAP];
    __shared__ int cnts[8];
    __shared__ int offs[9];
    const int cell = blockIdx.x;
    const int w    = threadIdx.x >> 5;
    const int lane = threadIdx.x & 31;

    int base = 0;
    const int j_beg = w * (KPTS / 8);
    const int j_end = j_beg + (KPTS / 8);
    for (int j0 = j_beg; j0 < j_end; j0 += 32) {
        int j = j0 + lane;
        float x = dom[j * 3 + 0];
        float y = dom[j * 3 + 1];
        float z = dom[j * 3 + 2];
        bool m = (cell_of(x, y, z) == cell);
        unsigned mask = __ballot_sync(0xffffffffu, m);
        if (m) {
            int pos = base + __popc(mask & ((1u << lane) - 1u));
            if (pos < CCAP) lists[w * CCAP + pos] = j;
        }
        base += __popc(mask);
    }
    if (lane == 0) cnts[w] = min(base, CCAP);
    __syncthreads();

    if (threadIdx.x == 0) {
        int acc = 0;
        for (int i = 0; i < 8; ++i) { offs[i] = acc; acc += cnts[i]; }
        offs[8] = acc;
        g_dcount[cell] = min(acc, DCAP);
    }
    __syncthreads();

    int cnt = cnts[w];
    int off = offs[w];
    for (int i = lane; i < cnt; i += 32) {
        int pos = off + i;
        if (pos < DCAP) g_dlist[cell * DCAP + pos] = lists[w * CCAP + i];
    }
}

// ---------------------------------------------------------------------------
// Per dom point: (kx, ky, kz, -L*|k|^2) as one float4.
// ---------------------------------------------------------------------------
__global__ void kcoef_kernel(const float* __restrict__ dom) {
    int k = blockIdx.x * blockDim.x + threadIdx.x;
    if (k >= KPTS) return;
    float x = dom[k * 3 + 0];
    float y = dom[k * 3 + 1];
    float z = dom[k * 3 + 2];
    g_kcoef[k] = make_float4(x, y, z, -LCONST * (x * x + y * y + z * z));
}

// ---------------------------------------------------------------------------
// theta[s][k] = sum over atoms within the 27-cell neighborhood of k's cell of
// exp2( ax*kx + ay*ky + az*kz + aw + c ). Dropped atoms (r >= 2.0) contribute
// < 2^-36 each -> total error < 1.5e-8, far below tolerance.
// Block per (cell, source); neighbor atoms staged in smem; uniform broadcast
// reads in the inner loop.
// ---------------------------------------------------------------------------
__global__ void __launch_bounds__(160) theta_kernel() {
    __shared__ float4 satoms[SCAP];
    const int cell = blockIdx.x;
    const int s    = blockIdx.y;
    const int tid  = threadIdx.x;
    const int cx = cell % NC, cy = (cell / NC) % NC, cz = cell / (NC * NC);

    // gather neighbor atoms (same traversal in every thread -> uniform base)
    int base = 0;
    for (int dz = -1; dz <= 1; ++dz)
        for (int dy = -1; dy <= 1; ++dy)
            for (int dx = -1; dx <= 1; ++dx) {
                int nx = cx + dx, ny = cy + dy, nz = cz + dz;
                if ((unsigned)nx >= NC || (unsigned)ny >= NC || (unsigned)nz >= NC)
                    continue;
                int ncell = (nz * NC + ny) * NC + nx;
                int cnt = g_acount[s * NCELLS + ncell];
                const float4* srcp = g_binned + (s * NCELLS + ncell) * ACAP;
                for (int i = tid; i < cnt; i += 160) {
                    int pos = base + i;
                    if (pos < SCAP) satoms[pos] = srcp[i];
                }
                base += cnt;
            }
    const int total = min(base, SCAP);
    __syncthreads();

    const int npts = g_dcount[cell];
    for (int p = tid; p < npts; p += 160) {
        const int idx = g_dlist[cell * DCAP + p];
        const float4 kc = g_kcoef[idx];
        float acc = 0.f;
        #pragma unroll 4
        for (int j = 0; j < total; ++j) {
            float4 a = satoms[j];
            float arg = fmaf(kc.x, a.x, fmaf(kc.y, a.y, fmaf(kc.z, a.z, a.w))) + kc.w;
            float e;
            asm("ex2.approx.ftz.f32 %0, %1;" : "=f"(e) : "f"(arg));
            acc += e;
        }
        g_theta[s * KPTS + idx] = acc;
    }
}

// ---------------------------------------------------------------------------
// out[b] = 1 - clip( scale * sum_k theta[b+1][k]*theta[0][k], 0, 1 )
// scale = A*V/sqrt(n1*n2) = 8 * (1000/16384) / 1024
// ---------------------------------------------------------------------------
__global__ void reduce_kernel(float* __restrict__ out) {
    __shared__ float red[256];
    const int b = blockIdx.x;
    const float* tb = g_theta + (size_t)(1 + b) * KPTS;
    const float* t0 = g_theta;
    float p = 0.f;
    for (int k = threadIdx.x; k < KPTS; k += 256)
        p += tb[k] * t0[k];
    red[threadIdx.x] = p;
    __syncthreads();
    for (int st = 128; st > 0; st >>= 1) {
        if (threadIdx.x < st) red[threadIdx.x] += red[threadIdx.x + st];
        __syncthreads();
    }
    if (threadIdx.x == 0) {
        float dot = 4.76837158203125e-4f * red[0];
        dot = fminf(fmaxf(dot, 0.f), 1.f);
        out[b] = 1.f - dot;
    }
}

extern "C" void kernel_launch(void* const* d_in, const int* in_sizes, int n_in,
                              void* d_out, int out_size) {
    const float* C1  = (const float*)d_in[0];   // (16, 1024, 3)
    const float* C   = (const float*)d_in[1];   // (1024, 3)
    const float* dom = (const float*)d_in[2];   // (16384, 3)

    bin_atoms_kernel<<<dim3(NCELLS, NSRC), 32>>>(C1, C);
    bin_dom_kernel<<<NCELLS, 256>>>(dom);
    kcoef_kernel<<<(KPTS + 255) / 256, 256>>>(dom);
    theta_kernel<<<dim3(NCELLS, NSRC), 160>>>();
    reduce_kernel<<<NB, 256>>>((float*)d_out);
}

// round 4
// speedup vs baseline: 1.8596x; 1.1600x over previous
#include <cuda_runtime.h>

#define KPTS   16384
#define NATOMS 1024
#define NB     16
#define NSRC   17      // source 0 = C, sources 1..16 = C1[b]
#define NC     5       // cells per axis (h = 2.0)
#define NCELLS 125
#define ACAP   40      // atoms per cell capacity (mean 8.2)
#define DCAP   512     // dom points per cell capacity (mean 131)
#define SCAP   448     // gathered neighbor-atom capacity (mean 221)
#define NPAIR  (SCAP / 2)

// L = inv2s * log2(e) = 2*pi * 1.4426950408889634
#define LCONST 9.064720283654388f

typedef unsigned long long u64;

// static scratch (no allocations allowed)
__device__ float4 g_binned[NSRC * NCELLS * ACAP];
__device__ int    g_acount[NSRC * NCELLS];
__device__ int    g_dlist[NCELLS * DCAP];
__device__ int    g_dcount[NCELLS];
__device__ float4 g_kcoef[KPTS];
__device__ float  g_theta[NSRC * KPTS];

__device__ __forceinline__ int cell_of(float x, float y, float z) {
    int cx = min(NC - 1, max(0, (int)(x * 0.5f)));
    int cy = min(NC - 1, max(0, (int)(y * 0.5f)));
    int cz = min(NC - 1, max(0, (int)(z * 0.5f)));
    return (cz * NC + cy) * NC + cx;
}

// ---- packed f32x2 helpers --------------------------------------------------
__device__ __forceinline__ u64 pk2(float lo, float hi) {
    u64 r; asm("mov.b64 %0, {%1, %2};" : "=l"(r) : "f"(lo), "f"(hi)); return r;
}
__device__ __forceinline__ void upk2(u64 v, float& lo, float& hi) {
    asm("mov.b64 {%0, %1}, %2;" : "=f"(lo), "=f"(hi) : "l"(v));
}
__device__ __forceinline__ u64 fma2(u64 a, u64 b, u64 c) {
    u64 r; asm("fma.rn.f32x2 %0, %1, %2, %3;" : "=l"(r) : "l"(a), "l"(b), "l"(c)); return r;
}
__device__ __forceinline__ u64 add2(u64 a, u64 b) {
    u64 r; asm("add.rn.f32x2 %0, %1, %2;" : "=l"(r) : "l"(a), "l"(b)); return r;
}
__device__ __forceinline__ float ex2(float a) {
    float e; asm("ex2.approx.ftz.f32 %0, %1;" : "=f"(e) : "f"(a)); return e;
}

// ---------------------------------------------------------------------------
// Single prep launch (18 blocks x 1024 threads).
// Block 0: dom binning (2-pass smem histogram; list order is irrelevant to the
//          FP result since each point's theta is computed independently) and
//          per-point coefficients (kx, ky, kz, -L*|k|^2).
// Blocks 1..17: deterministic atom binning for source s = blockIdx.x-1 via
//          smem-staged coords + match_any rank (atom index order preserved).
// ---------------------------------------------------------------------------
__global__ void __launch_bounds__(1024) prep_kernel(const float* __restrict__ C1,
                                                    const float* __restrict__ C,
                                                    const float* __restrict__ dom) {
    __shared__ float sx[NATOMS], sy[NATOMS], sz[NATOMS];
    __shared__ int   hist[NCELLS], offp[NCELLS];
    const int tid = threadIdx.x;

    if (blockIdx.x == 0) {
        // ---------------- dom binning + kcoef ----------------
        if (tid < NCELLS) { hist[tid] = 0; offp[tid] = 0; }
        __syncthreads();
        int mycell[KPTS / 1024];
        #pragma unroll
        for (int it = 0; it < KPTS / 1024; ++it) {
            int k = it * 1024 + tid;
            float x = dom[k * 3 + 0];
            float y = dom[k * 3 + 1];
            float z = dom[k * 3 + 2];
            g_kcoef[k] = make_float4(x, y, z, -LCONST * (x * x + y * y + z * z));
            int c = cell_of(x, y, z);
            mycell[it] = c;
            atomicAdd(&hist[c], 1);
        }
        __syncthreads();
        if (tid == 0) {
            #pragma unroll 1
            for (int c = 0; c < NCELLS; ++c) g_dcount[c] = min(hist[c], DCAP);
        }
        __syncthreads();
        #pragma unroll
        for (int it = 0; it < KPTS / 1024; ++it) {
            int k = it * 1024 + tid;
            int c = mycell[it];
            int slot = atomicAdd(&offp[c], 1);
            if (slot < DCAP) g_dlist[c * DCAP + slot] = k;
        }
    } else {
        // ---------------- atom binning (deterministic) ----------------
        const int s = blockIdx.x - 1;
        const float* src = (s == 0) ? C : (C1 + (size_t)(s - 1) * NATOMS * 3);
        if (tid < NATOMS) {
            sx[tid] = src[tid * 3 + 0];
            sy[tid] = src[tid * 3 + 1];
            sz[tid] = src[tid * 3 + 2];
        }
        if (tid < NCELLS) hist[tid] = 0;   // reuse hist as running offsets
        __syncthreads();
        if (tid < 32) {
            const int lane = tid;
            #pragma unroll 1
            for (int w = 0; w < NATOMS / 32; ++w) {
                int j = w * 32 + lane;
                float x = sx[j], y = sy[j], z = sz[j];
                int cell = cell_of(x, y, z);
                unsigned mm = __match_any_sync(0xffffffffu, cell);
                int rank = __popc(mm & ((1u << lane) - 1u));
                int pos = hist[cell] + rank;
                if (pos < ACAP) {
                    float phi = x * x + y * y + z * z;
                    g_binned[(s * NCELLS + cell) * ACAP + pos] =
                        make_float4(2.f * LCONST * x, 2.f * LCONST * y,
                                    2.f * LCONST * z, -LCONST * phi);
                }
                if (rank == 0) hist[cell] += __popc(mm);
                __syncwarp();
            }
            #pragma unroll 1
            for (int c = lane; c < NCELLS; c += 32)
                g_acount[s * NCELLS + c] = min(hist[c], ACAP);
        }
    }
}

// ---------------------------------------------------------------------------
// theta[s][k] = sum over neighbor-cell atoms of exp2(ax*kx+ay*ky+az*kz+aw+kw).
// Atoms processed in packed PAIRS via fma.rn.f32x2; odd count padded with a
// dummy atom (aw = -1e30 -> exp2 flushes to 0). Deterministic order.
// ---------------------------------------------------------------------------
__global__ void __launch_bounds__(160) theta_kernel() {
    __shared__ float4     satoms[SCAP];
    __shared__ ulonglong2 sA[NPAIR];    // (x0,x1),(y0,y1)
    __shared__ ulonglong2 sB[NPAIR];    // (z0,z1),(w0,w1)
    const int cell = blockIdx.x;
    const int s    = blockIdx.y;
    const int tid  = threadIdx.x;
    const int cx = cell % NC, cy = (cell / NC) % NC, cz = cell / (NC * NC);

    // gather neighbor atoms (uniform traversal)
    int base = 0;
    for (int dz = -1; dz <= 1; ++dz)
        for (int dy = -1; dy <= 1; ++dy)
            for (int dx = -1; dx <= 1; ++dx) {
                int nx = cx + dx, ny = cy + dy, nz = cz + dz;
                if ((unsigned)nx >= NC || (unsigned)ny >= NC || (unsigned)nz >= NC)
                    continue;
                int ncell = (nz * NC + ny) * NC + nx;
                int cnt = g_acount[s * NCELLS + ncell];
                const float4* srcp = g_binned + (s * NCELLS + ncell) * ACAP;
                for (int i = tid; i < cnt; i += 160) {
                    int pos = base + i;
                    if (pos < SCAP) satoms[pos] = srcp[i];
                }
                base += cnt;
            }
    int total = min(base, SCAP);
    if ((total & 1) && total < SCAP && tid == 0)
        satoms[total] = make_float4(0.f, 0.f, 0.f, -1e30f);
    const int npairs = (total + 1) >> 1;
    __syncthreads();

    // pack atom pairs for f32x2 consumption
    for (int jp = tid; jp < npairs; jp += 160) {
        float4 a = satoms[2 * jp];
        float4 b = satoms[2 * jp + 1];
        sA[jp] = make_ulonglong2(pk2(a.x, b.x), pk2(a.y, b.y));
        sB[jp] = make_ulonglong2(pk2(a.z, b.z), pk2(a.w, b.w));
    }
    __syncthreads();

    const int npts = g_dcount[cell];
    for (int p = tid; p < npts; p += 160) {
        const int idx = g_dlist[cell * DCAP + p];
        const float4 kc = g_kcoef[idx];
        const u64 kx2 = pk2(kc.x, kc.x);
        const u64 ky2 = pk2(kc.y, kc.y);
        const u64 kz2 = pk2(kc.z, kc.z);
        const u64 kw2 = pk2(kc.w, kc.w);
        u64 acc = 0ull;                       // (0.f, 0.f)
        #pragma unroll 4
        for (int jp = 0; jp < npairs; ++jp) {
            ulonglong2 A = sA[jp];
            ulonglong2 B = sB[jp];
            u64 t = add2(B.y, kw2);
            t = fma2(kz2, B.x, t);
            t = fma2(ky2, A.y, t);
            t = fma2(kx2, A.x, t);
            float lo, hi; upk2(t, lo, hi);
            acc = add2(acc, pk2(ex2(lo), ex2(hi)));
        }
        float a0, a1; upk2(acc, a0, a1);
        g_theta[s * KPTS + idx] = a0 + a1;
    }
}

// ---------------------------------------------------------------------------
// out[b] = 1 - clip( scale * sum_k theta[b+1][k]*theta[0][k], 0, 1 )
// scale = A*V/sqrt(n1*n2) = 8 * (1000/16384) / 1024
// ---------------------------------------------------------------------------
__global__ void reduce_kernel(float* __restrict__ out) {
    __shared__ float red[256];
    const int b = blockIdx.x;
    const float* tb = g_theta + (size_t)(1 + b) * KPTS;
    const float* t0 = g_theta;
    float p = 0.f;
    for (int k = threadIdx.x; k < KPTS; k += 256)
        p += tb[k] * t0[k];
    red[threadIdx.x] = p;
    __syncthreads();
    for (int st = 128; st > 0; st >>= 1) {
        if (threadIdx.x < st) red[threadIdx.x] += red[threadIdx.x + st];
        __syncthreads();
    }
    if (threadIdx.x == 0) {
        float dot = 4.76837158203125e-4f * red[0];
        dot = fminf(fmaxf(dot, 0.f), 1.f);
        out[b] = 1.f - dot;
    }
}

extern "C" void kernel_launch(void* const* d_in, const int* in_sizes, int n_in,
                              void* d_out, int out_size) {
    const float* C1  = (const float*)d_in[0];   // (16, 1024, 3)
    const float* C   = (const float*)d_in[1];   // (1024, 3)
    const float* dom = (const float*)d_in[2];   // (16384, 3)

    prep_kernel<<<1 + NSRC, 1024>>>(C1, C, dom);
    theta_kernel<<<dim3(NCELLS, NSRC), 160>>>();
    reduce_kernel<<<NB, 256>>>((float*)d_out);
}

// round 7
// speedup vs baseline: 1.9070x; 1.0255x over previous
#include <cuda_runtime.h>

#define KPTS   16384
#define NATOMS 1024
#define NB     16
#define NSRC   17      // source 0 = C, sources 1..16 = C1[b]
#define NC     5       // cells per axis (h = 2.0)
#define NCELLS 125
#define ACAP   40      // atoms per cell capacity (mean 8.2)
#define DCAP   512     // dom points per cell capacity (mean 131)
#define SCAP   448     // gathered neighbor-atom capacity (mean 221)
#define NPAIR  (SCAP / 2)

// L = inv2s * log2(e) = 2*pi * 1.4426950408889634
#define LCONST 9.064720283654388f

typedef unsigned long long u64;

// static scratch (no allocations allowed)
__device__ float4 g_binned[NSRC * NCELLS * ACAP];
__device__ int    g_acount[NSRC * NCELLS];
__device__ int    g_dlist[NCELLS * DCAP];
__device__ int    g_dcount[NCELLS];
__device__ float4 g_kcoef[KPTS];
__device__ float  g_theta[NSRC * KPTS];

__device__ __forceinline__ int cell_of(float x, float y, float z) {
    int cx = min(NC - 1, max(0, (int)(x * 0.5f)));
    int cy = min(NC - 1, max(0, (int)(y * 0.5f)));
    int cz = min(NC - 1, max(0, (int)(z * 0.5f)));
    return (cz * NC + cy) * NC + cx;
}

// ---- packed f32x2 helpers --------------------------------------------------
__device__ __forceinline__ u64 pk2(float lo, float hi) {
    u64 r; asm("mov.b64 %0, {%1, %2};" : "=l"(r) : "f"(lo), "f"(hi)); return r;
}
__device__ __forceinline__ void upk2(u64 v, float& lo, float& hi) {
    asm("mov.b64 {%0, %1}, %2;" : "=f"(lo), "=f"(hi) : "l"(v));
}
__device__ __forceinline__ u64 fma2(u64 a, u64 b, u64 c) {
    u64 r; asm("fma.rn.f32x2 %0, %1, %2, %3;" : "=l"(r) : "l"(a), "l"(b), "l"(c)); return r;
}
__device__ __forceinline__ u64 add2(u64 a, u64 b) {
    u64 r; asm("add.rn.f32x2 %0, %1, %2;" : "=l"(r) : "l"(a), "l"(b)); return r;
}
__device__ __forceinline__ float ex2(float a) {
    float e; asm("ex2.approx.ftz.f32 %0, %1;" : "=f"(e) : "f"(a)); return e;
}

// ---------------------------------------------------------------------------
// Single prep launch (18 blocks x 1024 threads), fully parallel.
// Block 0: dom binning (smem histogram; dlist order within a cell does not
//          affect any FP value: each point's theta is written to g_theta[idx]
//          independent of its list position) + per-point coefficients.
// Blocks 1..17: DETERMINISTIC atom binning for source s = blockIdx.x-1:
//          thread = atom; per-warp per-cell counts via match_any leaders;
//          across-warp exclusive prefix done in parallel (one thread per
//          cell); final slot = warp_base + intra-warp rank. Atom index order
//          is preserved -> fixed summation order in theta.
// ---------------------------------------------------------------------------
__global__ void __launch_bounds__(1024) prep_kernel(const float* __restrict__ C1,
                                                    const float* __restrict__ C,
                                                    const float* __restrict__ dom) {
    const int tid = threadIdx.x;

    if (blockIdx.x == 0) {
        // ---------------- dom binning + kcoef ----------------
        __shared__ int hist[NCELLS], offp[NCELLS];
        if (tid < NCELLS) { hist[tid] = 0; offp[tid] = 0; }
        __syncthreads();
        int mycell[KPTS / 1024];
        #pragma unroll
        for (int it = 0; it < KPTS / 1024; ++it) {
            int k = it * 1024 + tid;
            float x = dom[k * 3 + 0];
            float y = dom[k * 3 + 1];
            float z = dom[k * 3 + 2];
            g_kcoef[k] = make_float4(x, y, z, -LCONST * (x * x + y * y + z * z));
            int c = cell_of(x, y, z);
            mycell[it] = c;
            atomicAdd(&hist[c], 1);
        }
        __syncthreads();
        if (tid < NCELLS) g_dcount[tid] = min(hist[tid], DCAP);
        #pragma unroll
        for (int it = 0; it < KPTS / 1024; ++it) {
            int k = it * 1024 + tid;
            int c = mycell[it];
            int slot = atomicAdd(&offp[c], 1);
            if (slot < DCAP) g_dlist[c * DCAP + slot] = k;
        }
    } else {
        // ---------------- atom binning (parallel, deterministic) -------
        __shared__ int wcnt[32 * 128];           // [warp][cell], row 128 ints
        const int s = blockIdx.x - 1;
        const float* src = (s == 0) ? C : (C1 + (size_t)(s - 1) * NATOMS * 3);
        const int lane = tid & 31;
        const int w    = tid >> 5;

        #pragma unroll
        for (int i = 0; i < 4; ++i) wcnt[tid + i * 1024] = 0;

        const float x = src[tid * 3 + 0];
        const float y = src[tid * 3 + 1];
        const float z = src[tid * 3 + 2];
        const int   c = cell_of(x, y, z);
        __syncthreads();

        unsigned mm  = __match_any_sync(0xffffffffu, c);
        int     rank = __popc(mm & ((1u << lane) - 1u));
        if (rank == 0) wcnt[w * 128 + c] = __popc(mm);
        __syncthreads();

        if (tid < NCELLS) {
            int acc = 0;
            #pragma unroll
            for (int ww = 0; ww < 32; ++ww) {
                int v = wcnt[ww * 128 + tid];
                wcnt[ww * 128 + tid] = acc;       // exclusive warp base
                acc += v;
            }
            g_acount[s * NCELLS + tid] = min(acc, ACAP);
        }
        __syncthreads();

        int pos = wcnt[w * 128 + c] + rank;
        if (pos < ACAP) {
            float phi = x * x + y * y + z * z;
            g_binned[(s * NCELLS + c) * ACAP + pos] =
                make_float4(2.f * LCONST * x, 2.f * LCONST * y,
                            2.f * LCONST * z, -LCONST * phi);
        }
    }
}

// ---------------------------------------------------------------------------
// theta[s][k] = sum over neighbor-cell atoms of exp2(ax*kx+ay*ky+az*kz+aw+kw).
// Atoms processed in packed PAIRS via fma.rn.f32x2; odd count padded with a
// dummy atom (aw = -1e30 -> exp2 flushes to 0). Deterministic order.
// ---------------------------------------------------------------------------
__global__ void __launch_bounds__(160) theta_kernel() {
    __shared__ float4     satoms[SCAP];
    __shared__ ulonglong2 sA[NPAIR];    // (x0,x1),(y0,y1)
    __shared__ ulonglong2 sB[NPAIR];    // (z0,z1),(w0,w1)
    __shared__ int        ncl[27];      // neighbor cell ids (-1 invalid)
    __shared__ int        scnt[27];     // neighbor cell atom counts
    const int cell = blockIdx.x;
    const int s    = blockIdx.y;
    const int tid  = threadIdx.x;
    const int cx = cell % NC, cy = (cell / NC) % NC, cz = cell / (NC * NC);

    // preload all neighbor counts in parallel (no dependent LDG chain)
    if (tid < 27) {
        int dx = tid % 3 - 1, dy = (tid / 3) % 3 - 1, dz = tid / 9 - 1;
        int nx = cx + dx, ny = cy + dy, nz = cz + dz;
        bool ok = (unsigned)nx < NC && (unsigned)ny < NC && (unsigned)nz < NC;
        int ncell = ok ? (nz * NC + ny) * NC + nx : -1;
        ncl[tid]  = ncell;
        scnt[tid] = ok ? g_acount[s * NCELLS + ncell] : 0;
    }
    __syncthreads();

    // gather neighbor atoms (uniform traversal; counts from smem broadcast)
    int base = 0;
    #pragma unroll 1
    for (int ci = 0; ci < 27; ++ci) {
        int cnt = scnt[ci];
        if (cnt) {
            const float4* srcp = g_binned + (s * NCELLS + ncl[ci]) * ACAP;
            for (int i = tid; i < cnt; i += 160) {
                int pos = base + i;
                if (pos < SCAP) satoms[pos] = srcp[i];
            }
            base += cnt;
        }
    }
    int total = min(base, SCAP);
    if ((total & 1) && total < SCAP && tid == 0)
        satoms[total] = make_float4(0.f, 0.f, 0.f, -1e30f);
    const int npairs = (total + 1) >> 1;
    __syncthreads();

    // pack atom pairs for f32x2 consumption
    for (int jp = tid; jp < npairs; jp += 160) {
        float4 a = satoms[2 * jp];
        float4 b = satoms[2 * jp + 1];
        sA[jp] = make_ulonglong2(pk2(a.x, b.x), pk2(a.y, b.y));
        sB[jp] = make_ulonglong2(pk2(a.z, b.z), pk2(a.w, b.w));
    }
    __syncthreads();

    const int npts = g_dcount[cell];
    for (int p = tid; p < npts; p += 160) {
        const int idx = g_dlist[cell * DCAP + p];
        const float4 kc = g_kcoef[idx];
        const u64 kx2 = pk2(kc.x, kc.x);
        const u64 ky2 = pk2(kc.y, kc.y);
        const u64 kz2 = pk2(kc.z, kc.z);
        const u64 kw2 = pk2(kc.w, kc.w);
        u64 acc = 0ull;                       // (0.f, 0.f)
        #pragma unroll 4
        for (int jp = 0; jp < npairs; ++jp) {
            ulonglong2 A = sA[jp];
            ulonglong2 B = sB[jp];
            u64 t = add2(B.y, kw2);
            t = fma2(kz2, B.x, t);
            t = fma2(ky2, A.y, t);
            t = fma2(kx2, A.x, t);
            float lo, hi; upk2(t, lo, hi);
            acc = add2(acc, pk2(ex2(lo), ex2(hi)));
        }
        float a0, a1; upk2(acc, a0, a1);
        g_theta[s * KPTS + idx] = a0 + a1;
    }
}

// ---------------------------------------------------------------------------
// out[b] = 1 - clip( scale * sum_k theta[b+1][k]*theta[0][k], 0, 1 )
// scale = A*V/sqrt(n1*n2) = 8 * (1000/16384) / 1024
// ---------------------------------------------------------------------------
__global__ void reduce_kernel(float* __restrict__ out) {
    __shared__ float red[256];
    const int b = blockIdx.x;
    const float* tb = g_theta + (size_t)(1 + b) * KPTS;
    const float* t0 = g_theta;
    float p = 0.f;
    for (int k = threadIdx.x; k < KPTS; k += 256)
        p += tb[k] * t0[k];
    red[threadIdx.x] = p;
    __syncthreads();
    for (int st = 128; st > 0; st >>= 1) {
        if (threadIdx.x < st) red[threadIdx.x] += red[threadIdx.x + st];
        __syncthreads();
    }
    if (threadIdx.x == 0) {
        float dot = 4.76837158203125e-4f * red[0];
        dot = fminf(fmaxf(dot, 0.f), 1.f);
        out[b] = 1.f - dot;
    }
}

extern "C" void kernel_launch(void* const* d_in, const int* in_sizes, int n_in,
                              void* d_out, int out_size) {
    const float* C1  = (const float*)d_in[0];   // (16, 1024, 3)
    const float* C   = (const float*)d_in[1];   // (1024, 3)
    const float* dom = (const float*)d_in[2];   // (16384, 3)

    prep_kernel<<<1 + NSRC, 1024>>>(C1, C, dom);
    theta_kernel<<<dim3(NCELLS, NSRC), 160>>>();
    reduce_kernel<<<NB, 256>>>((float*)d_out);
}